// round 6
// baseline (speedup 1.0000x reference)
#include <cuda_runtime.h>
#include <math.h>

// Problem constants
#define MTOT 32768      // B*T = 8*4096
#define DIN  512        // D
#define DC   256        // Dc
#define NQ   8
#define BINS 1024
#define RVQ_BLOCKS (MTOT / 128)   // 256

#define OUT_ELEMS   ((size_t)MTOT * DIN)        // 16777216
#define IDX_ELEMS   ((size_t)NQ * MTOT)         // 262144

typedef unsigned long long ull;

// Scratch (static device globals; allocation-free), 256B aligned for float4.
__device__ __align__(256) float  g_h[MTOT * DC];       // 32 MB
__device__ __align__(256) float  g_res[MTOT * DC];     // 32 MB
__device__ __align__(256) float  g_q[MTOT * DC];       // 32 MB (sum of gathered codewords)
__device__ __align__(256) float  g_e2[NQ * BINS];
__device__ __align__(256) double g_partial[NQ * RVQ_BLOCKS];
__device__ __align__(256) float  g_idx_sink[IDX_ELEMS];
__device__ __align__(256) float  g_commit_sink[16];

// ---------------------------------------------------------------------------
// Packed f32x2 helpers (sm_100+). fma.rn.f32x2 = two EXACT fp32 rn FMAs in one
// instruction -> bitwise identical to fmaf pairs, 2x FFMA issue throughput.
// ---------------------------------------------------------------------------
__device__ __forceinline__ void fma2(ull& c, ull a, ull b) {
    asm("fma.rn.f32x2 %0, %1, %2, %0;" : "+l"(c) : "l"(a), "l"(b));
}
__device__ __forceinline__ ull dup2(float x) {
    ull r; asm("mov.b64 %0, {%1, %1};" : "=l"(r) : "f"(x)); return r;
}
__device__ __forceinline__ float2 unpack2(ull v) {
    float2 f; asm("mov.b64 {%0, %1}, %2;" : "=f"(f.x), "=f"(f.y) : "l"(v)); return f;
}

// ---------------------------------------------------------------------------
// XLA/Eigen rational tanh for f32 (what jnp.tanh lowers to on GPU).
// ---------------------------------------------------------------------------
__device__ __forceinline__ float xla_tanh(float x) {
    float ax = fabsf(x);
    float xc = fminf(fmaxf(x, -9.0f), 9.0f);
    float x2 = __fmul_rn(xc, xc);
    float p = -2.76076847742355e-16f;
    p = __fadd_rn(__fmul_rn(p, x2),  2.00018790482477e-13f);
    p = __fadd_rn(__fmul_rn(p, x2), -8.60467152213735e-11f);
    p = __fadd_rn(__fmul_rn(p, x2),  5.12229709037114e-08f);
    p = __fadd_rn(__fmul_rn(p, x2),  1.48572235717979e-05f);
    p = __fadd_rn(__fmul_rn(p, x2),  6.37261928875436e-04f);
    p = __fadd_rn(__fmul_rn(p, x2),  4.89352455891786e-03f);
    float num = __fmul_rn(xc, p);
    float q = 1.19825839466702e-06f;
    q = __fadd_rn(__fmul_rn(q, x2), 1.18534705686654e-04f);
    q = __fadd_rn(__fmul_rn(q, x2), 2.26843463243900e-03f);
    q = __fadd_rn(__fmul_rn(q, x2), 4.89352518554385e-03f);
    float r = __fdiv_rn(num, q);
    return (ax < 0.0004f) ? x : r;
}

// ---------------------------------------------------------------------------
// XLA-style warp row reduction (fp32, no fma, ascending strided + shfl tree).
// ---------------------------------------------------------------------------
__device__ __forceinline__ float warp_rowsum_sq(const float* __restrict__ p, int lane) {
    float s = 0.f;
    #pragma unroll
    for (int t = 0; t < DC / 32; t++) {
        float v = p[lane + 32 * t];
        s = __fadd_rn(s, __fmul_rn(v, v));
    }
    #pragma unroll
    for (int o = 16; o; o >>= 1)
        s = __fadd_rn(s, __shfl_down_sync(0xffffffffu, s, o));
    return s;
}

__global__ void e2_kernel(const float* __restrict__ cb) {
    int warp = (blockIdx.x * blockDim.x + threadIdx.x) >> 5;
    int lane = threadIdx.x & 31;
    int nwarps = (gridDim.x * blockDim.x) >> 5;
    for (int row = warp; row < NQ * BINS; row += nwarps) {
        float s = warp_rowsum_sq(cb + (size_t)row * DC, lane);
        if (lane == 0) g_e2[row] = s;
    }
}

// ---------------------------------------------------------------------------
// proj_in: h = xla_tanh(x @ in_w^T + in_b). 128x128x16, f32x2 inner loop.
// A-tile stored duplicated (AsD[kk][2r]=[2r+1]) for direct 8B broadcast loads.
// Accumulation order = serial k-ascending rn FMA chain (bit-stable).
// ---------------------------------------------------------------------------
__global__ __launch_bounds__(256, 2)
void proj_in_kernel(const float* __restrict__ A,
                    const float* __restrict__ Bw,
                    const float* __restrict__ bias) {
    __shared__ __align__(16) float AsD[16][256];
    __shared__ __align__(16) float Bs[16][128];

    int tid = threadIdx.x;
    int tx = tid & 15, ty = tid >> 4;
    int rowBase = blockIdx.x * 128;
    int colBase = blockIdx.y * 128;

    ull acc2[8][4];
    #pragma unroll
    for (int i = 0; i < 8; i++)
        #pragma unroll
        for (int j = 0; j < 4; j++) acc2[i][j] = 0ull;

    for (int kc = 0; kc < DIN; kc += 16) {
        #pragma unroll
        for (int l = 0; l < 2; l++) {
            int id = tid + l * 256;
            int r = id >> 2, kq = (id & 3) * 4;
            float4 v = *(const float4*)(A + (size_t)(rowBase + r) * DIN + kc + kq);
            ((ull*)&AsD[kq + 0][0])[r] = dup2(v.x);
            ((ull*)&AsD[kq + 1][0])[r] = dup2(v.y);
            ((ull*)&AsD[kq + 2][0])[r] = dup2(v.z);
            ((ull*)&AsD[kq + 3][0])[r] = dup2(v.w);
            float4 b = *(const float4*)(Bw + (size_t)(colBase + r) * DIN + kc + kq);
            Bs[kq + 0][r] = b.x; Bs[kq + 1][r] = b.y;
            Bs[kq + 2][r] = b.z; Bs[kq + 3][r] = b.w;
        }
        __syncthreads();
        #pragma unroll
        for (int kk = 0; kk < 16; kk++) {
            const ull* ap = (const ull*)&AsD[kk][0];
            const ull* bp = (const ull*)&Bs[kk][tx * 8];
            ull b2[4];
            #pragma unroll
            for (int j = 0; j < 4; j++) b2[j] = bp[j];
            #pragma unroll
            for (int i = 0; i < 8; i++) {
                ull a2 = ap[ty * 8 + i];
                #pragma unroll
                for (int j = 0; j < 4; j++) fma2(acc2[i][j], a2, b2[j]);
            }
        }
        __syncthreads();
    }

    #pragma unroll
    for (int i = 0; i < 8; i++) {
        int row = rowBase + ty * 8 + i;
        #pragma unroll
        for (int j2 = 0; j2 < 4; j2++) {
            float2 p = unpack2(acc2[i][j2]);
            #pragma unroll
            for (int h = 0; h < 2; h++) {
                int col = colBase + tx * 8 + j2 * 2 + h;
                float pre = __fadd_rn(h ? p.y : p.x, bias[col]);
                float t = xla_tanh(pre);
                size_t off = (size_t)row * DC + col;
                g_h[off] = t;
                g_res[off] = t;
            }
        }
    }
}

// ---------------------------------------------------------------------------
// lexicographic (value, index) min
// ---------------------------------------------------------------------------
__device__ __forceinline__ void amin_merge(float& bv, int& bi, float v, int i) {
    if (v < bv || (v == bv && i < bi)) { bv = v; bi = i; }
}

// ---------------------------------------------------------------------------
// One RVQ step. dist = (r2 - 2*re) + e2 fp32; re via f32x2 FMA chain
// (bitwise == scalar fmaf chain); fp32 lexicographic argmin.
// ---------------------------------------------------------------------------
__global__ __launch_bounds__(256, 2)
void rvq_step_kernel(const float* __restrict__ cb_all, int step,
                     float* __restrict__ idx_out) {
    const float* cb = cb_all + (size_t)step * BINS * DC;
    const float* e2 = g_e2 + step * BINS;

    __shared__ __align__(16) float AsD[16][256];
    __shared__ __align__(16) float Bs[16][128];
    __shared__ float r2row[128];
    __shared__ float candV[128];
    __shared__ int   candI[128];
    __shared__ float bestV[128];
    __shared__ int   bestI[128];
    __shared__ double rs[256];

    int tid = threadIdx.x;
    int tx = tid & 15, ty = tid >> 4;
    int wid = tid >> 5, lane = tid & 31;
    int rowBase = blockIdx.x * 128;

    for (int r = wid * 16; r < wid * 16 + 16; r++) {
        float s = warp_rowsum_sq(g_res + (size_t)(rowBase + r) * DC, lane);
        if (lane == 0) r2row[r] = s;
    }
    if (tid < 128) { bestV[tid] = 3.4e38f; bestI[tid] = 0x7fffffff; }
    __syncthreads();

    for (int bc = 0; bc < BINS; bc += 128) {
        ull acc2[8][4];
        #pragma unroll
        for (int i = 0; i < 8; i++)
            #pragma unroll
            for (int j = 0; j < 4; j++) acc2[i][j] = 0ull;

        for (int kc = 0; kc < DC; kc += 16) {
            #pragma unroll
            for (int l = 0; l < 2; l++) {
                int id = tid + l * 256;
                int r = id >> 2, kq = (id & 3) * 4;
                float4 v = *(const float4*)(g_res + (size_t)(rowBase + r) * DC + kc + kq);
                ((ull*)&AsD[kq + 0][0])[r] = dup2(v.x);
                ((ull*)&AsD[kq + 1][0])[r] = dup2(v.y);
                ((ull*)&AsD[kq + 2][0])[r] = dup2(v.z);
                ((ull*)&AsD[kq + 3][0])[r] = dup2(v.w);
                float4 b = *(const float4*)(cb + (size_t)(bc + r) * DC + kc + kq);
                Bs[kq + 0][r] = b.x; Bs[kq + 1][r] = b.y;
                Bs[kq + 2][r] = b.z; Bs[kq + 3][r] = b.w;
            }
            __syncthreads();
            #pragma unroll
            for (int kk = 0; kk < 16; kk++) {
                const ull* ap = (const ull*)&AsD[kk][0];
                const ull* bp = (const ull*)&Bs[kk][tx * 8];
                ull b2[4];
                #pragma unroll
                for (int j = 0; j < 4; j++) b2[j] = bp[j];
                #pragma unroll
                for (int i = 0; i < 8; i++) {
                    ull a2 = ap[ty * 8 + i];
                    #pragma unroll
                    for (int j = 0; j < 4; j++) fma2(acc2[i][j], a2, b2[j]);
                }
            }
            __syncthreads();
        }

        float ee[8];
        #pragma unroll
        for (int j = 0; j < 8; j++) ee[j] = e2[bc + tx * 8 + j];

        #pragma unroll
        for (int i = 0; i < 8; i++) {
            int row = ty * 8 + i;
            float r2 = r2row[row];
            float bv = 3.4e38f; int bi = 0x7fffffff;
            #pragma unroll
            for (int j2 = 0; j2 < 4; j2++) {
                float2 p = unpack2(acc2[i][j2]);
                float d0 = __fadd_rn(__fsub_rn(r2, __fmul_rn(2.0f, p.x)), ee[j2 * 2 + 0]);
                amin_merge(bv, bi, d0, bc + tx * 8 + j2 * 2 + 0);
                float d1 = __fadd_rn(__fsub_rn(r2, __fmul_rn(2.0f, p.y)), ee[j2 * 2 + 1]);
                amin_merge(bv, bi, d1, bc + tx * 8 + j2 * 2 + 1);
            }
            #pragma unroll
            for (int m = 1; m <= 8; m <<= 1) {
                float ov = __shfl_xor_sync(0xffffffffu, bv, m);
                int   oi = __shfl_xor_sync(0xffffffffu, bi, m);
                amin_merge(bv, bi, ov, oi);
            }
            if (tx == 0) { candV[row] = bv; candI[row] = bi; }
        }
        __syncthreads();
        if (tid < 128) {
            float bv = bestV[tid]; int bi = bestI[tid];
            amin_merge(bv, bi, candV[tid], candI[tid]);
            bestV[tid] = bv; bestI[tid] = bi;
        }
        __syncthreads();
    }

    if (tid < 128)
        idx_out[(size_t)step * MTOT + rowBase + tid] = (float)bestI[tid];

    // gather + residual update + q accumulation + commit partial
    double csum = 0.0;
    for (int r = 0; r < 128; r++) {
        int gi = bestI[r];
        float c = cb[(size_t)gi * DC + tid];
        size_t off = (size_t)(rowBase + r) * DC + tid;
        float old = g_res[off];
        float t = __fsub_rn(c, old);
        csum += (double)__fmul_rn(t, t);
        g_res[off] = __fsub_rn(old, c);
        g_q[off] = (step == 0) ? c : __fadd_rn(g_q[off], c);
    }
    rs[tid] = csum;
    __syncthreads();
    #pragma unroll
    for (int s = 128; s; s >>= 1) {
        if (tid < s) rs[tid] += rs[tid + s];
        __syncthreads();
    }
    if (tid == 0) g_partial[step * RVQ_BLOCKS + blockIdx.x] = rs[0];
}

__global__ void finalize_kernel(float* __restrict__ commit_out) {
    if (blockIdx.x == 0 && threadIdx.x == 0) {
        double total = 0.0;
        for (int n = 0; n < NQ; n++) {
            double s = 0.0;
            for (int b = 0; b < RVQ_BLOCKS; b++) s += g_partial[n * RVQ_BLOCKS + b];
            total += s / ((double)MTOT * (double)DC);
        }
        *commit_out = (float)(0.1 * total);
    }
}

// ---------------------------------------------------------------------------
// proj_out: out = (h + (sumq - h)) @ out_w^T + out_b. f32x2 inner loop.
// ---------------------------------------------------------------------------
__global__ __launch_bounds__(256, 2)
void proj_out_kernel(const float* __restrict__ Bw,
                     const float* __restrict__ bias,
                     float* __restrict__ C) {
    __shared__ __align__(16) float AsD[16][256];
    __shared__ __align__(16) float Bs[16][128];

    int tid = threadIdx.x;
    int tx = tid & 15, ty = tid >> 4;
    int rowBase = blockIdx.x * 128;
    int colBase = blockIdx.y * 128;

    ull acc2[8][4];
    #pragma unroll
    for (int i = 0; i < 8; i++)
        #pragma unroll
        for (int j = 0; j < 4; j++) acc2[i][j] = 0ull;

    for (int kc = 0; kc < DC; kc += 16) {
        #pragma unroll
        for (int l = 0; l < 2; l++) {
            int id = tid + l * 256;
            int r = id >> 2, kq = (id & 3) * 4;
            size_t off = (size_t)(rowBase + r) * DC + kc + kq;
            float4 h4 = *(const float4*)(g_h + off);
            float4 q4 = *(const float4*)(g_q + off);
            // quantized = h + (sumq - h), elementwise, non-contracted
            float qx = __fadd_rn(h4.x, __fsub_rn(q4.x, h4.x));
            float qy = __fadd_rn(h4.y, __fsub_rn(q4.y, h4.y));
            float qz = __fadd_rn(h4.z, __fsub_rn(q4.z, h4.z));
            float qw = __fadd_rn(h4.w, __fsub_rn(q4.w, h4.w));
            ((ull*)&AsD[kq + 0][0])[r] = dup2(qx);
            ((ull*)&AsD[kq + 1][0])[r] = dup2(qy);
            ((ull*)&AsD[kq + 2][0])[r] = dup2(qz);
            ((ull*)&AsD[kq + 3][0])[r] = dup2(qw);
            float4 b = *(const float4*)(Bw + (size_t)(colBase + r) * DC + kc + kq);
            Bs[kq + 0][r] = b.x; Bs[kq + 1][r] = b.y;
            Bs[kq + 2][r] = b.z; Bs[kq + 3][r] = b.w;
        }
        __syncthreads();
        #pragma unroll
        for (int kk = 0; kk < 16; kk++) {
            const ull* ap = (const ull*)&AsD[kk][0];
            const ull* bp = (const ull*)&Bs[kk][tx * 8];
            ull b2[4];
            #pragma unroll
            for (int j = 0; j < 4; j++) b2[j] = bp[j];
            #pragma unroll
            for (int i = 0; i < 8; i++) {
                ull a2 = ap[ty * 8 + i];
                #pragma unroll
                for (int j = 0; j < 4; j++) fma2(acc2[i][j], a2, b2[j]);
            }
        }
        __syncthreads();
    }

    #pragma unroll
    for (int i = 0; i < 8; i++) {
        int row = rowBase + ty * 8 + i;
        #pragma unroll
        for (int j2 = 0; j2 < 4; j2++) {
            float2 p = unpack2(acc2[i][j2]);
            int col = colBase + tx * 8 + j2 * 2;
            C[(size_t)row * DIN + col]     = __fadd_rn(p.x, bias[col]);
            C[(size_t)row * DIN + col + 1] = __fadd_rn(p.y, bias[col + 1]);
        }
    }
}

// ---------------------------------------------------------------------------
extern "C" void kernel_launch(void* const* d_in, const int* in_sizes, int n_in,
                              void* d_out, int out_size) {
    const float* x     = (const float*)d_in[0];   // [8,4096,512]
    const float* in_w  = (const float*)d_in[1];   // [256,512]
    const float* in_b  = (const float*)d_in[2];   // [256]
    const float* out_w = (const float*)d_in[3];   // [512,256]
    const float* out_b = (const float*)d_in[4];   // [512]
    const float* cb    = (const float*)d_in[5];   // [8,1024,256]

    float* out_f = (float*)d_out;

    float* idx_f    = nullptr;
    float* commit_f = nullptr;
    if ((size_t)out_size >= OUT_ELEMS + IDX_ELEMS + 1) {
        idx_f    = out_f + OUT_ELEMS;
        commit_f = out_f + OUT_ELEMS + IDX_ELEMS;
    } else if ((size_t)out_size >= OUT_ELEMS + IDX_ELEMS) {
        idx_f = out_f + OUT_ELEMS;
    }
    if (!idx_f)    cudaGetSymbolAddress((void**)&idx_f,    g_idx_sink);
    if (!commit_f) cudaGetSymbolAddress((void**)&commit_f, g_commit_sink);

    e2_kernel<<<64, 256>>>(cb);

    {
        dim3 grid(MTOT / 128, DC / 128);
        proj_in_kernel<<<grid, 256>>>(x, in_w, in_b);
    }

    for (int n = 0; n < NQ; n++)
        rvq_step_kernel<<<RVQ_BLOCKS, 256>>>(cb, n, idx_f);

    finalize_kernel<<<1, 32>>>(commit_f);

    {
        dim3 grid(MTOT / 128, DIN / 128);
        proj_out_kernel<<<grid, 256>>>(out_w, out_b, out_f);
    }
}